// round 12
// baseline (speedup 1.0000x reference)
#include <cuda_runtime.h>
#include <cuda_fp16.h>

// SNN: B=4096, T=256, I=7, H=64, O=8
// 1 batch/warp, 2 hidden units/lane. R11: BOTH matvecs on tensor cores.
//   phase 0: cur1 = x@W1^T + b1 via HMMA (x hi+lo fp16 in the two k-halves
//            of one m16n8k16 A-tile; W1 hi/lo B-frags from smem tables)
//   phase 1: scalar recurrence reads precomputed cur pairs (1 LDS.64/step)
//   phase 2: outputs = spk@W2^T via HMMA (as before, W2 hi/lo split)

#define THRESH 1.0f
#define BETA 0.8f

typedef unsigned long long u64;
typedef unsigned int u32;

constexpr int T_ = 256;
constexpr int I_ = 7;
constexpr int H_ = 64;
constexpr int O_ = 8;
constexpr int WPB = 4;
constexpr int TCHUNK = 16;
constexpr int A_STRIDE   = 24;  // halves per A row (16 used + 8 pad) = 48B
constexpr int CUR_STRIDE = 68;  // floats per cur row (64 + 4 pad) = 272B
constexpr int SPK_STRIDE = 72;  // halves per spike row (64 + 8 pad) = 144B

__device__ __forceinline__ u32 packh2(__half a, __half b) {
    __half2 v = __halves2half2(a, b);
    return *reinterpret_cast<u32*>(&v);
}
__device__ __forceinline__ u32 cvt_f16x2(float lo, float hi) {
    u32 r; asm("cvt.rn.f16x2.f32 %0, %1, %2;" : "=r"(r) : "f"(hi), "f"(lo)); return r;
}
__device__ __forceinline__ void ldsm_x4(u32& r0, u32& r1, u32& r2, u32& r3, u32 addr) {
    asm volatile("ldmatrix.sync.aligned.m8n8.x4.shared.b16 {%0,%1,%2,%3}, [%4];"
                 : "=r"(r0), "=r"(r1), "=r"(r2), "=r"(r3) : "r"(addr));
}
__device__ __forceinline__ void mma16816(float& c0, float& c1, float& c2, float& c3,
                                         u32 a0, u32 a1, u32 a2, u32 a3,
                                         u32 b0, u32 b1) {
    asm volatile("mma.sync.aligned.m16n8k16.row.col.f32.f16.f16.f32 "
                 "{%0,%1,%2,%3},{%4,%5,%6,%7},{%8,%9},{%0,%1,%2,%3};"
                 : "+f"(c0), "+f"(c1), "+f"(c2), "+f"(c3)
                 : "r"(a0), "r"(a1), "r"(a2), "r"(a3), "r"(b0), "r"(b1));
}

__global__ __launch_bounds__(WPB * 32, 6)
void snn_kernel(const float* __restrict__ x,
                const float* __restrict__ hs,
                const float* __restrict__ W1,
                const float* __restrict__ b1,
                const float* __restrict__ W2,
                const float* __restrict__ b2,
                float* __restrict__ out,     // (B,T,8)
                float* __restrict__ newh,    // (B,T,64)
                int B)
{
    // Block-shared W1 fragment tables (same for every warp):
    //  w1tab[0][nt][lane]: lo32 = W1_hi pair (k0-7 half), hi32 = same (dup in k8-15)
    //  w1tab[1][nt][lane]: lo32 = W1_lo pair,             hi32 = 0
    __shared__ u64    w1tab[2][8][32];                               // 4 KB
    __shared__ float2 b1tab[8][32];                                  // 2 KB
    // Per-warp tiles:
    __shared__ __align__(16) __half        atile[WPB][TCHUNK * A_STRIDE];     // 3 KB
    __shared__ __align__(16) float         curt[WPB][TCHUNK * CUR_STRIDE];    // 17 KB
    __shared__ __align__(16) unsigned short spk[WPB][TCHUNK][SPK_STRIDE];     // 9 KB

    const int w    = threadIdx.x >> 5;
    const int lane = threadIdx.x & 31;
    const int b    = blockIdx.x * WPB + w;

    const int kp = 2 * (lane & 3);   // k-pair index for B frags; also D col pair

    // ---- build W1/b1 tables (warp 0 only) ----
    if (w == 0) {
        const int n_in = lane >> 2;
#pragma unroll
        for (int nt = 0; nt < 8; nt++) {
            const int n = nt * 8 + n_in;
            const float wv0 = (kp     < I_) ? W1[n * I_ + kp]     : 0.0f;
            const float wv1 = (kp + 1 < I_) ? W1[n * I_ + kp + 1] : 0.0f;
            const __half h0 = __float2half_rn(wv0);
            const __half h1 = __float2half_rn(wv1);
            const __half l0 = __float2half_rn(wv0 - __half2float(h0));
            const __half l1 = __float2half_rn(wv1 - __half2float(h1));
            const u32 hi01 = packh2(h0, h1);
            const u32 lo01 = packh2(l0, l1);
            w1tab[0][nt][lane] = ((u64)hi01 << 32) | (u64)hi01;
            w1tab[1][nt][lane] = (u64)lo01;
            b1tab[nt][lane] = make_float2(b1[nt * 8 + kp], b1[nt * 8 + kp + 1]);
        }
    }
    __syncthreads();

    if (b >= B) return;

    const int h0 = 2 * lane;

    // --- W2 B-fragments for the output GEMM (hi+lo fp16 split) ---
    u32 bhi[4][2], blo[4][2];
    {
        const int o = lane >> 2;
#pragma unroll
        for (int kt = 0; kt < 4; kt++) {
#pragma unroll
            for (int half = 0; half < 2; half++) {
                const int k = kt * 16 + half * 8 + kp;
                float wa = W2[o * H_ + k], wb = W2[o * H_ + k + 1];
                __half ha = __float2half_rn(wa);
                __half hb = __float2half_rn(wb);
                __half la = __float2half_rn(wa - __half2float(ha));
                __half lb = __float2half_rn(wb - __half2float(hb));
                bhi[kt][half] = packh2(ha, hb);
                blo[kt][half] = packh2(la, lb);
            }
        }
    }
    const float bi0 = b2[kp];
    const float bi1 = b2[kp + 1];

    // --- initial membrane + initial reset ---
    const float2 m2 = *reinterpret_cast<const float2*>(hs + (size_t)b * H_ + h0);
    float mem0 = m2.x, mem1 = m2.y;
    float s0 = (float)(mem0 > THRESH);
    float s1 = (float)(mem1 > THRESH);

    const float* xb = x    + (size_t)b * T_ * I_;
    float*       nh = newh + (size_t)b * T_ * H_ + h0;
    float*       ob = out  + (size_t)b * T_ * O_;

    const u32 abase = (u32)__cvta_generic_to_shared(&atile[w][0]);
    const u32 lm_a  = abase + (u32)(lane & 15) * (A_STRIDE * 2)
                            + (u32)(lane >> 4) * 16;
    const u32 spk_base = (u32)__cvta_generic_to_shared(&spk[w][0][0]);
    const u32 lm_s  = spk_base + (u32)(lane & 15) * (SPK_STRIDE * 2)
                               + (u32)(lane >> 4) * 16;

    // ---- prefetch chunk 0's x row (lane = timestep; lanes 0-15) ----
    float p0=0, p1=0, p2=0, p3=0, p4=0, p5=0, p6=0;
    if (lane < TCHUNK) {
        const float* src = xb + (size_t)lane * I_;
        p0 = __ldcs(src + 0); p1 = __ldcs(src + 1); p2 = __ldcs(src + 2);
        p3 = __ldcs(src + 3); p4 = __ldcs(src + 4); p5 = __ldcs(src + 5);
        p6 = __ldcs(src + 6);
    }

    for (int c0 = 0; c0 < T_; c0 += TCHUNK) {
        // ---- stage A-tile: x hi in k0-6, x lo in k8-14, zeros elsewhere ----
        if (lane < TCHUNK) {
            const __half h0h = __float2half_rn(p0), h1h = __float2half_rn(p1);
            const __half h2h = __float2half_rn(p2), h3h = __float2half_rn(p3);
            const __half h4h = __float2half_rn(p4), h5h = __float2half_rn(p5);
            const __half h6h = __float2half_rn(p6);
            const __half l0h = __float2half_rn(p0 - __half2float(h0h));
            const __half l1h = __float2half_rn(p1 - __half2float(h1h));
            const __half l2h = __float2half_rn(p2 - __half2float(h2h));
            const __half l3h = __float2half_rn(p3 - __half2float(h3h));
            const __half l4h = __float2half_rn(p4 - __half2float(h4h));
            const __half l5h = __float2half_rn(p5 - __half2float(h5h));
            const __half l6h = __float2half_rn(p6 - __half2float(h6h));
            const __half z  = __float2half_rn(0.0f);
            uint4 qa, qb;
            qa.x = packh2(h0h, h1h); qa.y = packh2(h2h, h3h);
            qa.z = packh2(h4h, h5h); qa.w = packh2(h6h, z);
            qb.x = packh2(l0h, l1h); qb.y = packh2(l2h, l3h);
            qb.z = packh2(l4h, l5h); qb.w = packh2(l6h, z);
            char* dst = (char*)&atile[w][0] + lane * (A_STRIDE * 2);
            *reinterpret_cast<uint4*>(dst)      = qa;
            *reinterpret_cast<uint4*>(dst + 16) = qb;
        }
        __syncwarp();

        // ---- prefetch next chunk's x (retires during phases 0-2) ----
        {
            const int cnext = (c0 + TCHUNK < T_) ? (c0 + TCHUNK) : c0;
            if (lane < TCHUNK) {
                const float* src = xb + (size_t)(cnext + lane) * I_;
                p0 = __ldcs(src + 0); p1 = __ldcs(src + 1); p2 = __ldcs(src + 2);
                p3 = __ldcs(src + 3); p4 = __ldcs(src + 4); p5 = __ldcs(src + 5);
                p6 = __ldcs(src + 6);
            }
        }

        // ---- phase 0: cur1 tile via HMMA ----
        {
            u32 a0, a1, a2, a3;
            ldsm_x4(a0, a1, a2, a3, lm_a);
            const int r = lane >> 2;
#pragma unroll
            for (int nt = 0; nt < 8; nt++) {
                const float2 bi = b1tab[nt][lane];
                float d0 = bi.x, d1 = bi.y, d2 = bi.x, d3 = bi.y;
                const u64 f0 = w1tab[0][nt][lane];
                mma16816(d0, d1, d2, d3, a0, a1, a2, a3, (u32)f0, (u32)(f0 >> 32));
                const u64 f1 = w1tab[1][nt][lane];
                mma16816(d0, d1, d2, d3, a0, a1, a2, a3, (u32)f1, (u32)(f1 >> 32));
                const int colb = nt * 8 + kp;
                *reinterpret_cast<float2*>(&curt[w][r * CUR_STRIDE + colb]) =
                    make_float2(d0, d1);
                *reinterpret_cast<float2*>(&curt[w][(r + 8) * CUR_STRIDE + colb]) =
                    make_float2(d2, d3);
            }
        }
        __syncwarp();

        // ---- phase 1: recurrence (cur precomputed; 4 fp32 ops/step) ----
#pragma unroll
        for (int tt = 0; tt < TCHUNK; tt++) {
            const int t = c0 + tt;
            const float2 cur =
                *reinterpret_cast<const float2*>(&curt[w][tt * CUR_STRIDE + h0]);

            mem0 = fmaf(BETA, mem0, cur.x) - s0;
            mem1 = fmaf(BETA, mem1, cur.y) - s1;

            __stcs(reinterpret_cast<float2*>(nh + (size_t)t * H_),
                   make_float2(mem0, mem1));

            s0 = (float)(mem0 > THRESH);
            s1 = (float)(mem1 > THRESH);

            *reinterpret_cast<u32*>(&spk[w][tt][h0]) = cvt_f16x2(s0, s1);
        }
        __syncwarp();

        // ---- phase 2: outputs via HMMA ----
        {
            float d0 = bi0, d1 = bi1, d2 = bi0, d3 = bi1;
#pragma unroll
            for (int kt = 0; kt < 4; kt++) {
                u32 a0, a1, a2, a3;
                ldsm_x4(a0, a1, a2, a3, lm_s + (u32)(kt * 32));
                mma16816(d0, d1, d2, d3, a0, a1, a2, a3, bhi[kt][0], bhi[kt][1]);
                mma16816(d0, d1, d2, d3, a0, a1, a2, a3, blo[kt][0], blo[kt][1]);
            }
            const int row = lane >> 2;
            __stcs(reinterpret_cast<float2*>(ob + (size_t)(c0 + row) * O_ + kp),
                   make_float2(d0, d1));
            __stcs(reinterpret_cast<float2*>(ob + (size_t)(c0 + row + 8) * O_ + kp),
                   make_float2(d2, d3));
        }
        __syncwarp();
    }
}

extern "C" void kernel_launch(void* const* d_in, const int* in_sizes, int n_in,
                              void* d_out, int out_size)
{
    const float* x  = (const float*)d_in[0];
    const float* hs = (const float*)d_in[1];
    const float* W1 = (const float*)d_in[2];
    const float* b1 = (const float*)d_in[3];
    const float* W2 = (const float*)d_in[4];
    const float* b2 = (const float*)d_in[5];

    const int B = in_sizes[1] / H_;

    float* out  = (float*)d_out;                       // (B,T,O)
    float* newh = (float*)d_out + (size_t)B * T_ * O_; // (B,T,H)

    const int blocks = (B + WPB - 1) / WPB;
    snn_kernel<<<blocks, WPB * 32>>>(x, hs, W1, b1, W2, b2, out, newh, B);
}

// round 13
// speedup vs baseline: 1.0559x; 1.0559x over previous
#include <cuda_runtime.h>
#include <cuda_fp16.h>

// SNN: B=4096, T=256, I=7, H=64, O=8
// 1 batch/warp, 2 hidden units/lane. Recurrence fp32 (f32x2 cur1), outputs
// via HMMA m16n8k16 (spikes exact fp16, W2 hi+lo split).
// R12: software pipeline — phase2 (HMMA) of chunk c-1 executes in the same
// straight-line region as phase1 of chunk c (double-buffered spike tile),
// so tensor/ldsm work fills the recurrence's stall holes. x prefetched in
// registers across chunks. Plain write-back stores.

#define THRESH 1.0f
#define BETA 0.8f

typedef unsigned long long u64;
typedef unsigned int u32;

constexpr int T_ = 256;
constexpr int I_ = 7;
constexpr int H_ = 64;
constexpr int O_ = 8;
constexpr int WPB = 4;
constexpr int TCHUNK = 16;
constexpr int NCHUNK = T_ / TCHUNK;   // 16
constexpr int SPK_STRIDE = 72;        // halves per spike row = 144B (16B mult)

__device__ __forceinline__ u64 pack2(float lo, float hi) {
    u64 r; asm("mov.b64 %0, {%1, %2};" : "=l"(r) : "f"(lo), "f"(hi)); return r;
}
__device__ __forceinline__ void unpack2(u64 v, float& lo, float& hi) {
    asm("mov.b64 {%0, %1}, %2;" : "=f"(lo), "=f"(hi) : "l"(v));
}
__device__ __forceinline__ u64 fma2(u64 a, u64 b, u64 c) {
    u64 d; asm("fma.rn.f32x2 %0, %1, %2, %3;" : "=l"(d) : "l"(a), "l"(b), "l"(c)); return d;
}
__device__ __forceinline__ u32 cvt_f16x2(float lo, float hi) {
    u32 r; asm("cvt.rn.f16x2.f32 %0, %1, %2;" : "=r"(r) : "f"(hi), "f"(lo)); return r;
}
__device__ __forceinline__ void ldsm_x4(u32& r0, u32& r1, u32& r2, u32& r3, u32 addr) {
    asm volatile("ldmatrix.sync.aligned.m8n8.x4.shared.b16 {%0,%1,%2,%3}, [%4];"
                 : "=r"(r0), "=r"(r1), "=r"(r2), "=r"(r3) : "r"(addr));
}
__device__ __forceinline__ void mma16816(float& c0, float& c1, float& c2, float& c3,
                                         u32 a0, u32 a1, u32 a2, u32 a3,
                                         u32 b0, u32 b1) {
    asm volatile("mma.sync.aligned.m16n8k16.row.col.f32.f16.f16.f32 "
                 "{%0,%1,%2,%3},{%4,%5,%6,%7},{%8,%9},{%0,%1,%2,%3};"
                 : "+f"(c0), "+f"(c1), "+f"(c2), "+f"(c3)
                 : "r"(a0), "r"(a1), "r"(a2), "r"(a3), "r"(b0), "r"(b1));
}

__global__ __launch_bounds__(WPB * 32, 7)
void snn_kernel(const float* __restrict__ x,
                const float* __restrict__ hs,
                const float* __restrict__ W1,
                const float* __restrict__ b1,
                const float* __restrict__ W2,
                const float* __restrict__ b2,
                float* __restrict__ out,     // (B,T,8)
                float* __restrict__ newh,    // (B,T,64)
                int B)
{
    // Single x buffer (consumed same iteration it is staged);
    // double-buffered spike tile (phase2 of c-1 overlaps phase1 of c).
    __shared__ __align__(16) u64 xs[WPB][TCHUNK * 4];                        // 2 KB
    __shared__ __align__(16) unsigned short spk[WPB][2][TCHUNK][SPK_STRIDE]; // 18 KB

    const int w    = threadIdx.x >> 5;
    const int lane = threadIdx.x & 31;
    const int b    = blockIdx.x * WPB + w;
    if (b >= B) return;

    const int h0 = 2 * lane;
    const int kp = 2 * (lane & 3);

    // --- W1 packed over input pairs (bias folded into accumulator init) ---
    u64 w1a[4], w1b[4];
#pragma unroll
    for (int k = 0; k < 3; k++) {
        w1a[k] = pack2(W1[h0 * I_ + 2 * k],       W1[h0 * I_ + 2 * k + 1]);
        w1b[k] = pack2(W1[(h0 + 1) * I_ + 2 * k], W1[(h0 + 1) * I_ + 2 * k + 1]);
    }
    w1a[3] = pack2(W1[h0 * I_ + 6], 0.0f);
    w1b[3] = pack2(W1[(h0 + 1) * I_ + 6], 0.0f);
    const u64 b1a = pack2(b1[h0], 0.0f);
    const u64 b1b = pack2(b1[h0 + 1], 0.0f);

    // --- W2 B-fragments (n8k16 col-major), hi+lo fp16 split ---
    u32 bhi[4][2], blo[4][2];
    {
        const int o = lane >> 2;
#pragma unroll
        for (int kt = 0; kt < 4; kt++) {
#pragma unroll
            for (int half = 0; half < 2; half++) {
                const int k = kt * 16 + half * 8 + kp;
                float wa = W2[o * H_ + k], wb = W2[o * H_ + k + 1];
                __half ha = __float2half_rn(wa);
                __half hb = __float2half_rn(wb);
                __half la = __float2half_rn(wa - __half2float(ha));
                __half lb = __float2half_rn(wb - __half2float(hb));
                __half2 vh = __halves2half2(ha, hb);
                __half2 vl = __halves2half2(la, lb);
                bhi[kt][half] = *reinterpret_cast<u32*>(&vh);
                blo[kt][half] = *reinterpret_cast<u32*>(&vl);
            }
        }
    }
    const float bi0 = b2[kp];
    const float bi1 = b2[kp + 1];

    // --- initial membrane + initial reset ---
    const float2 m2 = *reinterpret_cast<const float2*>(hs + (size_t)b * H_ + h0);
    float mem0 = m2.x, mem1 = m2.y;
    float s0 = (float)(mem0 > THRESH);
    float s1 = (float)(mem1 > THRESH);

    const float* xb = x    + (size_t)b * T_ * I_;
    float*       nh = newh + (size_t)b * T_ * H_ + h0;
    float*       ob = out  + (size_t)b * T_ * O_;

    const u32 s_base0 = (u32)__cvta_generic_to_shared(&spk[w][0][0][0]);
    const u32 s_base1 = (u32)__cvta_generic_to_shared(&spk[w][1][0][0]);
    const u32 lm_off  = (u32)(lane & 15) * (SPK_STRIDE * 2) + (u32)(lane >> 4) * 16;

    // ---- prefetch chunk 0's x row (lane = timestep; lanes 0-15) ----
    float p0=0, p1=0, p2=0, p3=0, p4=0, p5=0, p6=0;
    if (lane < TCHUNK) {
        const float* src = xb + (size_t)lane * I_;
        p0 = src[0]; p1 = src[1]; p2 = src[2]; p3 = src[3];
        p4 = src[4]; p5 = src[5]; p6 = src[6];
    }

    for (int c = 0; c < NCHUNK; c++) {
        const int buf = c & 1;
        __syncwarp();

        // ---- stage prefetched x into smem (2 STS.128 per active lane) ----
        if (lane < TCHUNK) {
            ulonglong2 lo, hi;
            lo.x = pack2(p0, p1); lo.y = pack2(p2, p3);
            hi.x = pack2(p4, p5); hi.y = pack2(p6, 0.0f);
            *reinterpret_cast<ulonglong2*>(&xs[w][lane * 4])     = lo;
            *reinterpret_cast<ulonglong2*>(&xs[w][lane * 4 + 2]) = hi;
        }
        // ---- issue LDGs for the next chunk (retire during the body) ----
        {
            const int cnext = (c + 1 < NCHUNK) ? (c + 1) : c;
            if (lane < TCHUNK) {
                const float* src = xb + (size_t)(cnext * TCHUNK + lane) * I_;
                p0 = src[0]; p1 = src[1]; p2 = src[2]; p3 = src[3];
                p4 = src[4]; p5 = src[5]; p6 = src[6];
            }
        }
        __syncwarp();

        // ---- phase 2 of chunk c-1 (reads spk[buf^1]) — interleaves with
        //      phase 1 below: independent pipes, same basic block ----
        if (c > 0) {
            const u32 base = (buf ? s_base0 : s_base1) + lm_off;
            float d0 = bi0, d1 = bi1, d2 = bi0, d3 = bi1;
#pragma unroll
            for (int kt = 0; kt < 4; kt++) {
                u32 a0, a1, a2, a3;
                ldsm_x4(a0, a1, a2, a3, base + (u32)(kt * 32));
                mma16816(d0, d1, d2, d3, a0, a1, a2, a3, bhi[kt][0], bhi[kt][1]);
                mma16816(d0, d1, d2, d3, a0, a1, a2, a3, blo[kt][0], blo[kt][1]);
            }
            const int row = (c - 1) * TCHUNK + (lane >> 2);
            *reinterpret_cast<float2*>(ob + (size_t)row * O_ + kp) =
                make_float2(d0, d1);
            *reinterpret_cast<float2*>(ob + (size_t)(row + 8) * O_ + kp) =
                make_float2(d2, d3);
        }

        // ---- phase 1: recurrence over 16 steps (writes spk[buf]) ----
#pragma unroll
        for (int tt = 0; tt < TCHUNK; tt++) {
            const int t = c * TCHUNK + tt;
            const ulonglong2 xlo = *reinterpret_cast<const ulonglong2*>(&xs[w][tt * 4]);
            const ulonglong2 xhi = *reinterpret_cast<const ulonglong2*>(&xs[w][tt * 4 + 2]);

            u64 aa = fma2(xlo.x, w1a[0],
                     fma2(xlo.y, w1a[1],
                     fma2(xhi.x, w1a[2],
                     fma2(xhi.y, w1a[3], b1a))));
            u64 ab = fma2(xlo.x, w1b[0],
                     fma2(xlo.y, w1b[1],
                     fma2(xhi.x, w1b[2],
                     fma2(xhi.y, w1b[3], b1b))));
            float a0, a1, c0f, c1f;
            unpack2(aa, a0, a1); c0f = a0 + a1;
            unpack2(ab, a0, a1); c1f = a0 + a1;

            mem0 = fmaf(BETA, mem0, c0f) - s0;
            mem1 = fmaf(BETA, mem1, c1f) - s1;

            *reinterpret_cast<float2*>(nh + (size_t)t * H_) =
                make_float2(mem0, mem1);

            s0 = (float)(mem0 > THRESH);
            s1 = (float)(mem1 > THRESH);

            *reinterpret_cast<u32*>(&spk[w][buf][tt][h0]) = cvt_f16x2(s0, s1);
        }
    }

    // ---- drain: phase 2 of the last chunk ----
    __syncwarp();
    {
        const u32 base = ((NCHUNK - 1) & 1 ? s_base1 : s_base0) + lm_off;
        float d0 = bi0, d1 = bi1, d2 = bi0, d3 = bi1;
#pragma unroll
        for (int kt = 0; kt < 4; kt++) {
            u32 a0, a1, a2, a3;
            ldsm_x4(a0, a1, a2, a3, base + (u32)(kt * 32));
            mma16816(d0, d1, d2, d3, a0, a1, a2, a3, bhi[kt][0], bhi[kt][1]);
            mma16816(d0, d1, d2, d3, a0, a1, a2, a3, blo[kt][0], blo[kt][1]);
        }
        const int row = (NCHUNK - 1) * TCHUNK + (lane >> 2);
        *reinterpret_cast<float2*>(ob + (size_t)row * O_ + kp) =
            make_float2(d0, d1);
        *reinterpret_cast<float2*>(ob + (size_t)(row + 8) * O_ + kp) =
            make_float2(d2, d3);
    }
}

extern "C" void kernel_launch(void* const* d_in, const int* in_sizes, int n_in,
                              void* d_out, int out_size)
{
    const float* x  = (const float*)d_in[0];
    const float* hs = (const float*)d_in[1];
    const float* W1 = (const float*)d_in[2];
    const float* b1 = (const float*)d_in[3];
    const float* W2 = (const float*)d_in[4];
    const float* b2 = (const float*)d_in[5];

    const int B = in_sizes[1] / H_;

    float* out  = (float*)d_out;                       // (B,T,O)
    float* newh = (float*)d_out + (size_t)B * T_ * O_; // (B,T,H)

    const int blocks = (B + WPB - 1) / WPB;
    snn_kernel<<<blocks, WPB * 32>>>(x, hs, W1, b1, W2, b2, out, newh, B);
}